// round 2
// baseline (speedup 1.0000x reference)
#include <cuda_runtime.h>
#include <cfloat>

#define VOCAB 30522
#define MAX_DOCS 500000
#define HIT_CAP (1 << 23)   // 8M hit slots (expected ~67K)
#define TOPK 10
#define NB1 64              // top-k pass-1 blocks

// ---- device scratch (static: no allocations allowed) ----
__device__ float g_scores[MAX_DOCS];
__device__ int   g_hit_pos[HIT_CAP];
__device__ float g_hit_val[HIT_CAP];
__device__ int   g_nhits;
__device__ float g_cand_v[NB1 * TOPK];
__device__ int   g_cand_i[NB1 * TOPK];

// ---------------------------------------------------------------------------
// Kernel Z: zero scores + hit counter
// ---------------------------------------------------------------------------
__global__ void zero_kernel(int n_docs) {
    int t = blockIdx.x * blockDim.x + threadIdx.x;
    if (t == 0) g_nhits = 0;
    int stride = gridDim.x * blockDim.x;
    for (int i = t; i < n_docs; i += stride) g_scores[i] = 0.0f;
}

// ---------------------------------------------------------------------------
// Kernel A: stream nnz (coalesced int4), smem dense-query lookup, compact hits
// ---------------------------------------------------------------------------
__global__ void __launch_bounds__(1024, 1)
score_kernel(const int* __restrict__ qidx, const float* __restrict__ qval, int qn,
             const int* __restrict__ indice, const float* __restrict__ values,
             int nnz)
{
    extern __shared__ float qtab[];   // VOCAB floats = 122088 B
    for (int i = threadIdx.x; i < VOCAB; i += 1024) qtab[i] = 0.0f;
    __syncthreads();
    if (threadIdx.x < qn) atomicAdd(&qtab[qidx[threadIdx.x]], qval[threadIdx.x]);
    __syncthreads();

    const int gtid = blockIdx.x * 1024 + threadIdx.x;
    const int gsz  = gridDim.x * 1024;
    const int total4 = nnz >> 2;
    const int4* __restrict__ ind4 = (const int4*)indice;

    #pragma unroll 4
    for (int i = gtid; i < total4; i += gsz) {
        int4 t = ind4[i];
        float q0 = qtab[t.x];
        float q1 = qtab[t.y];
        float q2 = qtab[t.z];
        float q3 = qtab[t.w];
        int j = i << 2;
        if (q0 != 0.0f) {
            int p = atomicAdd(&g_nhits, 1);
            if (p < HIT_CAP) { g_hit_pos[p] = j;     g_hit_val[p] = q0 * values[j];     }
        }
        if (q1 != 0.0f) {
            int p = atomicAdd(&g_nhits, 1);
            if (p < HIT_CAP) { g_hit_pos[p] = j + 1; g_hit_val[p] = q1 * values[j + 1]; }
        }
        if (q2 != 0.0f) {
            int p = atomicAdd(&g_nhits, 1);
            if (p < HIT_CAP) { g_hit_pos[p] = j + 2; g_hit_val[p] = q2 * values[j + 2]; }
        }
        if (q3 != 0.0f) {
            int p = atomicAdd(&g_nhits, 1);
            if (p < HIT_CAP) { g_hit_pos[p] = j + 3; g_hit_val[p] = q3 * values[j + 3]; }
        }
    }

    // tail (nnz % 4 elements)
    int tail0 = total4 << 2;
    int j = tail0 + gtid;
    if (j < nnz) {
        float q = qtab[indice[j]];
        if (q != 0.0f) {
            int p = atomicAdd(&g_nhits, 1);
            if (p < HIT_CAP) { g_hit_pos[p] = j; g_hit_val[p] = q * values[j]; }
        }
    }
}

// ---------------------------------------------------------------------------
// Kernel B: per-hit binary search on crow (int32! JAX x64-disabled downcasts
// the numpy int64 to int32), scatter-add scores. crow is 2MB -> L2 resident.
// ---------------------------------------------------------------------------
__global__ void resolve_kernel(const int* __restrict__ crow, int n_docs) {
    int nh = g_nhits;
    if (nh > HIT_CAP) nh = HIT_CAP;
    int stride = gridDim.x * blockDim.x;
    for (int t = blockIdx.x * blockDim.x + threadIdx.x; t < nh; t += stride) {
        int j = g_hit_pos[t];
        // find largest d with crow[d] <= j  (searchsorted right - 1)
        int lo = 0, hi = n_docs;
        while (lo < hi) {
            int mid = (lo + hi + 1) >> 1;
            if (crow[mid] <= j) lo = mid; else hi = mid - 1;
        }
        atomicAdd(&g_scores[lo], g_hit_val[t]);
    }
}

// ---------------------------------------------------------------------------
// Top-k pass 1: each of NB1 blocks emits its local top-10
// ---------------------------------------------------------------------------
__global__ void topk1_kernel(int n_docs) {
    float lv[TOPK];
    int   li[TOPK];
    #pragma unroll
    for (int k = 0; k < TOPK; k++) { lv[k] = -FLT_MAX; li[k] = 0x7fffffff; }

    int gtid = blockIdx.x * blockDim.x + threadIdx.x;
    int gsz  = gridDim.x * blockDim.x;
    for (int d = gtid; d < n_docs; d += gsz) {
        float s = g_scores[d];
        if (s > lv[TOPK - 1]) {
            lv[TOPK - 1] = s; li[TOPK - 1] = d;
            #pragma unroll
            for (int k = TOPK - 1; k > 0; k--) {
                bool sw = (lv[k] > lv[k - 1]) ||
                          (lv[k] == lv[k - 1] && li[k] < li[k - 1]);
                if (sw) {
                    float tv = lv[k]; lv[k] = lv[k - 1]; lv[k - 1] = tv;
                    int   ti = li[k]; li[k] = li[k - 1]; li[k - 1] = ti;
                }
            }
        }
    }

    __shared__ float sv[256 * TOPK];
    __shared__ int   si[256 * TOPK];
    #pragma unroll
    for (int k = 0; k < TOPK; k++) {
        sv[threadIdx.x * TOPK + k] = lv[k];
        si[threadIdx.x * TOPK + k] = li[k];
    }
    __syncthreads();

    __shared__ float rv[256];
    __shared__ int   ri[256];
    __shared__ int   rs[256];

    for (int r = 0; r < TOPK; r++) {
        float bv = -FLT_MAX; int bi = 0x7fffffff; int bs = -1;
        for (int p = threadIdx.x; p < 256 * TOPK; p += 256) {
            float v = sv[p]; int idx = si[p];
            if (v > bv || (v == bv && idx < bi)) { bv = v; bi = idx; bs = p; }
        }
        rv[threadIdx.x] = bv; ri[threadIdx.x] = bi; rs[threadIdx.x] = bs;
        __syncthreads();
        for (int off = 128; off; off >>= 1) {
            if (threadIdx.x < off) {
                float ov = rv[threadIdx.x + off]; int oi = ri[threadIdx.x + off];
                if (ov > rv[threadIdx.x] ||
                    (ov == rv[threadIdx.x] && oi < ri[threadIdx.x])) {
                    rv[threadIdx.x] = ov; ri[threadIdx.x] = oi;
                    rs[threadIdx.x] = rs[threadIdx.x + off];
                }
            }
            __syncthreads();
        }
        if (threadIdx.x == 0) {
            g_cand_v[blockIdx.x * TOPK + r] = rv[0];
            g_cand_i[blockIdx.x * TOPK + r] = ri[0];
            if (rs[0] >= 0) { sv[rs[0]] = -FLT_MAX; si[rs[0]] = 0x7fffffff; }
        }
        __syncthreads();
    }
}

// ---------------------------------------------------------------------------
// Top-k pass 2: merge NB1*TOPK candidates, write final output
// out layout: [TOPK values][TOPK indices-as-float]
// ---------------------------------------------------------------------------
__global__ void topk2_kernel(float* __restrict__ out, int out_size) {
    const int NC = NB1 * TOPK;   // 640
    __shared__ float sv[NC];
    __shared__ int   si[NC];
    for (int p = threadIdx.x; p < NC; p += 256) { sv[p] = g_cand_v[p]; si[p] = g_cand_i[p]; }
    __syncthreads();

    __shared__ float rv[256];
    __shared__ int   ri[256];
    __shared__ int   rs[256];
    __shared__ float fv[TOPK];
    __shared__ int   fi[TOPK];

    for (int r = 0; r < TOPK; r++) {
        float bv = -FLT_MAX; int bi = 0x7fffffff; int bs = -1;
        for (int p = threadIdx.x; p < NC; p += 256) {
            float v = sv[p]; int idx = si[p];
            if (v > bv || (v == bv && idx < bi)) { bv = v; bi = idx; bs = p; }
        }
        rv[threadIdx.x] = bv; ri[threadIdx.x] = bi; rs[threadIdx.x] = bs;
        __syncthreads();
        for (int off = 128; off; off >>= 1) {
            if (threadIdx.x < off) {
                float ov = rv[threadIdx.x + off]; int oi = ri[threadIdx.x + off];
                if (ov > rv[threadIdx.x] ||
                    (ov == rv[threadIdx.x] && oi < ri[threadIdx.x])) {
                    rv[threadIdx.x] = ov; ri[threadIdx.x] = oi;
                    rs[threadIdx.x] = rs[threadIdx.x + off];
                }
            }
            __syncthreads();
        }
        if (threadIdx.x == 0) {
            fv[r] = rv[0]; fi[r] = ri[0];
            if (rs[0] >= 0) { sv[rs[0]] = -FLT_MAX; si[rs[0]] = 0x7fffffff; }
        }
        __syncthreads();
    }

    if (threadIdx.x < TOPK) {
        int k = threadIdx.x;
        if (k < out_size) out[k] = fv[k];
        if (TOPK + k < out_size) out[TOPK + k] = (float)fi[k];
    }
}

// ---------------------------------------------------------------------------
// kernel_launch
// Input order (metadata): q_indices(i32,32) q_values(f32,32) crow(i32,N+1)
//                         indice(i32,nnz) values(f32,nnz) [top_k]
// ---------------------------------------------------------------------------
extern "C" void kernel_launch(void* const* d_in, const int* in_sizes, int n_in,
                              void* d_out, int out_size) {
    const int*   qidx   = (const int*)d_in[0];
    const float* qval   = (const float*)d_in[1];
    const int*   crow   = (const int*)d_in[2];
    const int*   indice = (const int*)d_in[3];
    const float* values = (const float*)d_in[4];

    int qn     = in_sizes[0];
    int n_docs = in_sizes[2] - 1;
    int nnz    = in_sizes[3];
    if (n_docs > MAX_DOCS) n_docs = MAX_DOCS;

    const int SMEM_Q = VOCAB * (int)sizeof(float);
    cudaFuncSetAttribute(score_kernel, cudaFuncAttributeMaxDynamicSharedMemorySize, SMEM_Q);

    zero_kernel<<<256, 256>>>(n_docs);
    score_kernel<<<152, 1024, SMEM_Q>>>(qidx, qval, qn, indice, values, nnz);
    resolve_kernel<<<256, 256>>>(crow, n_docs);
    topk1_kernel<<<NB1, 256>>>(n_docs);
    topk2_kernel<<<1, 256>>>((float*)d_out, out_size);
}

// round 3
// speedup vs baseline: 1.0731x; 1.0731x over previous
#include <cuda_runtime.h>
#include <cfloat>

#define VOCAB 30522
#define MAX_DOCS 500000
#define HIT_CAP (1 << 23)   // 8M hit slots (expected ~67K)
#define TOPK 10
#define NB1 128             // top-k pass-1 blocks

// ---- device scratch (static: no allocations allowed) ----
__device__ float g_scores[MAX_DOCS];
__device__ int   g_hit_pos[HIT_CAP];
__device__ float g_hit_val[HIT_CAP];
__device__ int   g_nhits;
__device__ float g_cand_v[NB1 * TOPK];
__device__ int   g_cand_i[NB1 * TOPK];

// ---------------------------------------------------------------------------
// Kernel Z: zero scores (float4) + hit counter
// ---------------------------------------------------------------------------
__global__ void zero_kernel(int n_docs) {
    int t = blockIdx.x * blockDim.x + threadIdx.x;
    if (t == 0) g_nhits = 0;
    int stride = gridDim.x * blockDim.x;
    int n4 = n_docs >> 2;
    float4* s4 = (float4*)g_scores;
    float4 z = make_float4(0.f, 0.f, 0.f, 0.f);
    for (int i = t; i < n4; i += stride) s4[i] = z;
    int tail = n4 << 2;
    int j = tail + t;
    if (j < n_docs) g_scores[j] = 0.0f;
}

// ---------------------------------------------------------------------------
// Kernel A: stream nnz (coalesced int4), smem dense-query lookup, compact hits
// ---------------------------------------------------------------------------
__global__ void __launch_bounds__(1024, 1)
score_kernel(const int* __restrict__ qidx, const float* __restrict__ qval, int qn,
             const int* __restrict__ indice, const float* __restrict__ values,
             int nnz)
{
    extern __shared__ float qtab[];   // VOCAB floats = 122088 B
    for (int i = threadIdx.x; i < VOCAB; i += 1024) qtab[i] = 0.0f;
    __syncthreads();
    if (threadIdx.x < qn) atomicAdd(&qtab[qidx[threadIdx.x]], qval[threadIdx.x]);
    __syncthreads();

    const int gtid = blockIdx.x * 1024 + threadIdx.x;
    const int gsz  = gridDim.x * 1024;
    const int total4 = nnz >> 2;
    const int4* __restrict__ ind4 = (const int4*)indice;

    #pragma unroll 4
    for (int i = gtid; i < total4; i += gsz) {
        int4 t = ind4[i];
        float q0 = qtab[t.x];
        float q1 = qtab[t.y];
        float q2 = qtab[t.z];
        float q3 = qtab[t.w];
        int j = i << 2;
        if (q0 != 0.0f) {
            int p = atomicAdd(&g_nhits, 1);
            if (p < HIT_CAP) { g_hit_pos[p] = j;     g_hit_val[p] = q0 * values[j];     }
        }
        if (q1 != 0.0f) {
            int p = atomicAdd(&g_nhits, 1);
            if (p < HIT_CAP) { g_hit_pos[p] = j + 1; g_hit_val[p] = q1 * values[j + 1]; }
        }
        if (q2 != 0.0f) {
            int p = atomicAdd(&g_nhits, 1);
            if (p < HIT_CAP) { g_hit_pos[p] = j + 2; g_hit_val[p] = q2 * values[j + 2]; }
        }
        if (q3 != 0.0f) {
            int p = atomicAdd(&g_nhits, 1);
            if (p < HIT_CAP) { g_hit_pos[p] = j + 3; g_hit_val[p] = q3 * values[j + 3]; }
        }
    }

    // tail (nnz % 4 elements)
    int tail0 = total4 << 2;
    int j = tail0 + gtid;
    if (j < nnz) {
        float q = qtab[indice[j]];
        if (q != 0.0f) {
            int p = atomicAdd(&g_nhits, 1);
            if (p < HIT_CAP) { g_hit_pos[p] = j; g_hit_val[p] = q * values[j]; }
        }
    }
}

// ---------------------------------------------------------------------------
// Kernel B: per-hit binary search on crow (int32, L2-resident), scatter-add
// ---------------------------------------------------------------------------
__global__ void resolve_kernel(const int* __restrict__ crow, int n_docs) {
    int nh = g_nhits;
    if (nh > HIT_CAP) nh = HIT_CAP;
    int stride = gridDim.x * blockDim.x;
    for (int t = blockIdx.x * blockDim.x + threadIdx.x; t < nh; t += stride) {
        int j = g_hit_pos[t];
        int lo = 0, hi = n_docs;
        while (lo < hi) {
            int mid = (lo + hi + 1) >> 1;
            if (crow[mid] <= j) lo = mid; else hi = mid - 1;
        }
        atomicAdd(&g_scores[lo], g_hit_val[t]);
    }
}

// ---------------------------------------------------------------------------
// Top-k pass 1: NB1 blocks, float4 streaming, per-block top-10
// ---------------------------------------------------------------------------
__global__ void __launch_bounds__(256)
topk1_kernel(int n_docs) {
    float lv[TOPK];
    int   li[TOPK];
    #pragma unroll
    for (int k = 0; k < TOPK; k++) { lv[k] = -FLT_MAX; li[k] = 0x7fffffff; }

    int gtid = blockIdx.x * blockDim.x + threadIdx.x;
    int gsz  = gridDim.x * blockDim.x;

    int n4 = n_docs >> 2;
    const float4* __restrict__ s4 = (const float4*)g_scores;

    for (int i = gtid; i < n4; i += gsz) {
        float4 v = s4[i];
        int d = i << 2;
        #pragma unroll
        for (int e = 0; e < 4; e++) {
            float s = (e == 0) ? v.x : (e == 1) ? v.y : (e == 2) ? v.z : v.w;
            if (s > lv[TOPK - 1]) {
                int di = d + e;
                lv[TOPK - 1] = s; li[TOPK - 1] = di;
                #pragma unroll
                for (int k = TOPK - 1; k > 0; k--) {
                    bool sw = (lv[k] > lv[k - 1]) ||
                              (lv[k] == lv[k - 1] && li[k] < li[k - 1]);
                    if (sw) {
                        float tv = lv[k]; lv[k] = lv[k - 1]; lv[k - 1] = tv;
                        int   ti = li[k]; li[k] = li[k - 1]; li[k - 1] = ti;
                    }
                }
            }
        }
    }
    // scalar tail
    int tail = n4 << 2;
    for (int d = tail + gtid; d < n_docs; d += gsz) {
        float s = g_scores[d];
        if (s > lv[TOPK - 1]) {
            lv[TOPK - 1] = s; li[TOPK - 1] = d;
            #pragma unroll
            for (int k = TOPK - 1; k > 0; k--) {
                bool sw = (lv[k] > lv[k - 1]) ||
                          (lv[k] == lv[k - 1] && li[k] < li[k - 1]);
                if (sw) {
                    float tv = lv[k]; lv[k] = lv[k - 1]; lv[k - 1] = tv;
                    int   ti = li[k]; li[k] = li[k - 1]; li[k - 1] = ti;
                }
            }
        }
    }

    __shared__ float sv[256 * TOPK];
    __shared__ int   si[256 * TOPK];
    #pragma unroll
    for (int k = 0; k < TOPK; k++) {
        sv[threadIdx.x * TOPK + k] = lv[k];
        si[threadIdx.x * TOPK + k] = li[k];
    }
    __syncthreads();

    __shared__ float rv[256];
    __shared__ int   ri[256];
    __shared__ int   rs[256];

    for (int r = 0; r < TOPK; r++) {
        float bv = -FLT_MAX; int bi = 0x7fffffff; int bs = -1;
        for (int p = threadIdx.x; p < 256 * TOPK; p += 256) {
            float v = sv[p]; int idx = si[p];
            if (v > bv || (v == bv && idx < bi)) { bv = v; bi = idx; bs = p; }
        }
        rv[threadIdx.x] = bv; ri[threadIdx.x] = bi; rs[threadIdx.x] = bs;
        __syncthreads();
        for (int off = 128; off; off >>= 1) {
            if (threadIdx.x < off) {
                float ov = rv[threadIdx.x + off]; int oi = ri[threadIdx.x + off];
                if (ov > rv[threadIdx.x] ||
                    (ov == rv[threadIdx.x] && oi < ri[threadIdx.x])) {
                    rv[threadIdx.x] = ov; ri[threadIdx.x] = oi;
                    rs[threadIdx.x] = rs[threadIdx.x + off];
                }
            }
            __syncthreads();
        }
        if (threadIdx.x == 0) {
            g_cand_v[blockIdx.x * TOPK + r] = rv[0];
            g_cand_i[blockIdx.x * TOPK + r] = ri[0];
            if (rs[0] >= 0) { sv[rs[0]] = -FLT_MAX; si[rs[0]] = 0x7fffffff; }
        }
        __syncthreads();
    }
}

// ---------------------------------------------------------------------------
// Top-k pass 2: merge NB1*TOPK candidates, write final output
// out layout: [TOPK values][TOPK indices-as-float]
// ---------------------------------------------------------------------------
__global__ void topk2_kernel(float* __restrict__ out, int out_size) {
    const int NC = NB1 * TOPK;   // 1280
    __shared__ float sv[NC];
    __shared__ int   si[NC];
    for (int p = threadIdx.x; p < NC; p += 256) { sv[p] = g_cand_v[p]; si[p] = g_cand_i[p]; }
    __syncthreads();

    __shared__ float rv[256];
    __shared__ int   ri[256];
    __shared__ int   rs[256];
    __shared__ float fv[TOPK];
    __shared__ int   fi[TOPK];

    for (int r = 0; r < TOPK; r++) {
        float bv = -FLT_MAX; int bi = 0x7fffffff; int bs = -1;
        for (int p = threadIdx.x; p < NC; p += 256) {
            float v = sv[p]; int idx = si[p];
            if (v > bv || (v == bv && idx < bi)) { bv = v; bi = idx; bs = p; }
        }
        rv[threadIdx.x] = bv; ri[threadIdx.x] = bi; rs[threadIdx.x] = bs;
        __syncthreads();
        for (int off = 128; off; off >>= 1) {
            if (threadIdx.x < off) {
                float ov = rv[threadIdx.x + off]; int oi = ri[threadIdx.x + off];
                if (ov > rv[threadIdx.x] ||
                    (ov == rv[threadIdx.x] && oi < ri[threadIdx.x])) {
                    rv[threadIdx.x] = ov; ri[threadIdx.x] = oi;
                    rs[threadIdx.x] = rs[threadIdx.x + off];
                }
            }
            __syncthreads();
        }
        if (threadIdx.x == 0) {
            fv[r] = rv[0]; fi[r] = ri[0];
            if (rs[0] >= 0) { sv[rs[0]] = -FLT_MAX; si[rs[0]] = 0x7fffffff; }
        }
        __syncthreads();
    }

    if (threadIdx.x < TOPK) {
        int k = threadIdx.x;
        if (k < out_size) out[k] = fv[k];
        if (TOPK + k < out_size) out[TOPK + k] = (float)fi[k];
    }
}

// ---------------------------------------------------------------------------
// kernel_launch
// Input order (metadata): q_indices(i32,32) q_values(f32,32) crow(i32,N+1)
//                         indice(i32,nnz) values(f32,nnz) [top_k]
// ---------------------------------------------------------------------------
extern "C" void kernel_launch(void* const* d_in, const int* in_sizes, int n_in,
                              void* d_out, int out_size) {
    const int*   qidx   = (const int*)d_in[0];
    const float* qval   = (const float*)d_in[1];
    const int*   crow   = (const int*)d_in[2];
    const int*   indice = (const int*)d_in[3];
    const float* values = (const float*)d_in[4];

    int qn     = in_sizes[0];
    int n_docs = in_sizes[2] - 1;
    int nnz    = in_sizes[3];
    if (n_docs > MAX_DOCS) n_docs = MAX_DOCS;

    const int SMEM_Q = VOCAB * (int)sizeof(float);
    cudaFuncSetAttribute(score_kernel, cudaFuncAttributeMaxDynamicSharedMemorySize, SMEM_Q);

    zero_kernel<<<512, 256>>>(n_docs);
    score_kernel<<<148, 1024, SMEM_Q>>>(qidx, qval, qn, indice, values, nnz);
    resolve_kernel<<<256, 256>>>(crow, n_docs);
    topk1_kernel<<<NB1, 256>>>(n_docs);
    topk2_kernel<<<1, 256>>>((float*)d_out, out_size);
}

// round 4
// speedup vs baseline: 1.1411x; 1.0633x over previous
#include <cuda_runtime.h>
#include <cfloat>
#include <climits>

#define VOCAB 30522
#define MAX_DOCS 500000
#define HIT_CAP (1 << 23)
#define TOPK 10
#define NB1 296             // top-k pass-1 blocks (2 waves of 148)

// ---- device scratch ----
__device__ float g_scores[MAX_DOCS];
__device__ int   g_hit_pos[HIT_CAP];
__device__ float g_hit_val[HIT_CAP];
__device__ int   g_nhits;
__device__ float g_cand_v[NB1 * TOPK];
__device__ int   g_cand_i[NB1 * TOPK];

// ---------------------------------------------------------------------------
// zero scores (float4) + hit counter
// ---------------------------------------------------------------------------
__global__ void zero_kernel(int n_docs) {
    int t = blockIdx.x * blockDim.x + threadIdx.x;
    if (t == 0) g_nhits = 0;
    int stride = gridDim.x * blockDim.x;
    int n4 = n_docs >> 2;
    float4* s4 = (float4*)g_scores;
    float4 z = make_float4(0.f, 0.f, 0.f, 0.f);
    for (int i = t; i < n4; i += stride) s4[i] = z;
    int j = (n4 << 2) + t;
    if (j < n_docs) g_scores[j] = 0.0f;
}

// ---------------------------------------------------------------------------
// score: stream nnz, 4x-batched int4 loads (MLP>=4), smem query table lookup,
// compact hits to global buffer
// ---------------------------------------------------------------------------
__device__ __forceinline__ void emit_hit(float q, int j, const float* __restrict__ values) {
    if (q != 0.0f) {
        int p = atomicAdd(&g_nhits, 1);
        if (p < HIT_CAP) { g_hit_pos[p] = j; g_hit_val[p] = q * __ldg(values + j); }
    }
}

__global__ void __launch_bounds__(1024, 1)
score_kernel(const int* __restrict__ qidx, const float* __restrict__ qval, int qn,
             const int* __restrict__ indice, const float* __restrict__ values,
             int nnz)
{
    extern __shared__ float qtab[];   // VOCAB floats = 122088 B
    for (int i = threadIdx.x; i < VOCAB; i += 1024) qtab[i] = 0.0f;
    __syncthreads();
    if (threadIdx.x < qn) atomicAdd(&qtab[qidx[threadIdx.x]], qval[threadIdx.x]);
    __syncthreads();

    const int gtid = blockIdx.x * 1024 + threadIdx.x;
    const int gsz  = gridDim.x * 1024;
    const int total4 = nnz >> 2;
    const int4* __restrict__ ind4 = (const int4*)indice;

    int i = gtid;
    // batched main loop: 4 independent coalesced LDG.128 before any consume
    for (; i + 3 * gsz < total4; i += 4 * gsz) {
        int4 a = __ldcs(ind4 + i);
        int4 b = __ldcs(ind4 + i + gsz);
        int4 c = __ldcs(ind4 + i + 2 * gsz);
        int4 d = __ldcs(ind4 + i + 3 * gsz);

        float qa0 = qtab[a.x], qa1 = qtab[a.y], qa2 = qtab[a.z], qa3 = qtab[a.w];
        float qb0 = qtab[b.x], qb1 = qtab[b.y], qb2 = qtab[b.z], qb3 = qtab[b.w];
        float qc0 = qtab[c.x], qc1 = qtab[c.y], qc2 = qtab[c.z], qc3 = qtab[c.w];
        float qd0 = qtab[d.x], qd1 = qtab[d.y], qd2 = qtab[d.z], qd3 = qtab[d.w];

        int ja = i << 2, jb = (i + gsz) << 2, jc = (i + 2 * gsz) << 2, jd = (i + 3 * gsz) << 2;
        emit_hit(qa0, ja, values);     emit_hit(qa1, ja + 1, values);
        emit_hit(qa2, ja + 2, values); emit_hit(qa3, ja + 3, values);
        emit_hit(qb0, jb, values);     emit_hit(qb1, jb + 1, values);
        emit_hit(qb2, jb + 2, values); emit_hit(qb3, jb + 3, values);
        emit_hit(qc0, jc, values);     emit_hit(qc1, jc + 1, values);
        emit_hit(qc2, jc + 2, values); emit_hit(qc3, jc + 3, values);
        emit_hit(qd0, jd, values);     emit_hit(qd1, jd + 1, values);
        emit_hit(qd2, jd + 2, values); emit_hit(qd3, jd + 3, values);
    }
    // remainder int4s
    for (; i < total4; i += gsz) {
        int4 a = __ldcs(ind4 + i);
        float q0 = qtab[a.x], q1 = qtab[a.y], q2 = qtab[a.z], q3 = qtab[a.w];
        int j = i << 2;
        emit_hit(q0, j, values);     emit_hit(q1, j + 1, values);
        emit_hit(q2, j + 2, values); emit_hit(q3, j + 3, values);
    }
    // scalar tail (nnz % 4)
    int j = (total4 << 2) + gtid;
    if (j < nnz) {
        float q = qtab[indice[j]];
        emit_hit(q, j, values);
    }
}

// ---------------------------------------------------------------------------
// resolve: per-hit binary search on int32 crow (L2-resident), scatter-add
// ---------------------------------------------------------------------------
__global__ void resolve_kernel(const int* __restrict__ crow, int n_docs) {
    int nh = g_nhits;
    if (nh > HIT_CAP) nh = HIT_CAP;
    int stride = gridDim.x * blockDim.x;
    for (int t = blockIdx.x * blockDim.x + threadIdx.x; t < nh; t += stride) {
        int j = g_hit_pos[t];
        int lo = 0, hi = n_docs;
        while (lo < hi) {
            int mid = (lo + hi + 1) >> 1;
            if (crow[mid] <= j) lo = mid; else hi = mid - 1;
        }
        atomicAdd(&g_scores[lo], g_hit_val[t]);
    }
}

// ---------------------------------------------------------------------------
// top-k helpers: per-thread sorted top-10 + warp/block shuffle merges
// ---------------------------------------------------------------------------
__device__ __forceinline__ void insert10(float* lv, int* li, float s, int d) {
    if (s > lv[TOPK - 1] || (s == lv[TOPK - 1] && d < li[TOPK - 1])) {
        lv[TOPK - 1] = s; li[TOPK - 1] = d;
        #pragma unroll
        for (int k = TOPK - 1; k > 0; k--) {
            bool sw = (lv[k] > lv[k - 1]) ||
                      (lv[k] == lv[k - 1] && li[k] < li[k - 1]);
            if (sw) {
                float tv = lv[k]; lv[k] = lv[k - 1]; lv[k - 1] = tv;
                int   ti = li[k]; li[k] = li[k - 1]; li[k - 1] = ti;
            }
        }
    }
}

// merge 32 per-lane sorted lists -> lane0 gets block of 10 written to out
__device__ __forceinline__ void warp_merge10(float* lv, int* li,
                                             float* out_v, int* out_i) {
    int lane = threadIdx.x & 31;
    int p = 0;
    #pragma unroll
    for (int r = 0; r < TOPK; r++) {
        float bv = (p < TOPK) ? lv[p] : -FLT_MAX;
        int   bi = (p < TOPK) ? li[p] : INT_MAX;
        int   bl = lane;
        #pragma unroll
        for (int off = 16; off; off >>= 1) {
            float ov = __shfl_down_sync(0xffffffffu, bv, off);
            int   oi = __shfl_down_sync(0xffffffffu, bi, off);
            int   ol = __shfl_down_sync(0xffffffffu, bl, off);
            if (ov > bv || (ov == bv && oi < bi)) { bv = ov; bi = oi; bl = ol; }
        }
        bl = __shfl_sync(0xffffffffu, bl, 0);
        float wv = __shfl_sync(0xffffffffu, bv, 0);
        int   wi = __shfl_sync(0xffffffffu, bi, 0);
        if (lane == bl) p++;
        if (lane == 0) { out_v[r] = wv; out_i[r] = wi; }
    }
}

// warp 0 merges nwarp sorted lists of 10 (in smem) -> out[0..9]
__device__ __forceinline__ void block_merge10(const float* sv, const int* si,
                                              int nwarp, float* out_v, int* out_i) {
    int lane = threadIdx.x & 31;
    int p = 0;
    #pragma unroll
    for (int r = 0; r < TOPK; r++) {
        float bv = (lane < nwarp && p < TOPK) ? sv[lane * TOPK + p] : -FLT_MAX;
        int   bi = (lane < nwarp && p < TOPK) ? si[lane * TOPK + p] : INT_MAX;
        int   bl = lane;
        #pragma unroll
        for (int off = 16; off; off >>= 1) {
            float ov = __shfl_down_sync(0xffffffffu, bv, off);
            int   oi = __shfl_down_sync(0xffffffffu, bi, off);
            int   ol = __shfl_down_sync(0xffffffffu, bl, off);
            if (ov > bv || (ov == bv && oi < bi)) { bv = ov; bi = oi; bl = ol; }
        }
        bl = __shfl_sync(0xffffffffu, bl, 0);
        float wv = __shfl_sync(0xffffffffu, bv, 0);
        int   wi = __shfl_sync(0xffffffffu, bi, 0);
        if (lane == bl) p++;
        if (lane == 0) { out_v[r] = wv; out_i[r] = wi; }
    }
}

// ---------------------------------------------------------------------------
// top-k pass 1: NB1 blocks x 256, float4 stream, hierarchical merge (2 BARs)
// ---------------------------------------------------------------------------
__global__ void __launch_bounds__(256)
topk1_kernel(int n_docs) {
    float lv[TOPK]; int li[TOPK];
    #pragma unroll
    for (int k = 0; k < TOPK; k++) { lv[k] = -FLT_MAX; li[k] = INT_MAX; }

    int gtid = blockIdx.x * blockDim.x + threadIdx.x;
    int gsz  = gridDim.x * blockDim.x;
    int n4 = n_docs >> 2;
    const float4* __restrict__ s4 = (const float4*)g_scores;

    for (int i = gtid; i < n4; i += gsz) {
        float4 v = s4[i];
        int d = i << 2;
        insert10(lv, li, v.x, d);
        insert10(lv, li, v.y, d + 1);
        insert10(lv, li, v.z, d + 2);
        insert10(lv, li, v.w, d + 3);
    }
    for (int d = (n4 << 2) + gtid; d < n_docs; d += gsz)
        insert10(lv, li, g_scores[d], d);

    __shared__ float sv[8 * TOPK];
    __shared__ int   si[8 * TOPK];
    int wid = threadIdx.x >> 5;
    warp_merge10(lv, li, sv + wid * TOPK, si + wid * TOPK);
    __syncthreads();
    if (wid == 0)
        block_merge10(sv, si, 8, g_cand_v + blockIdx.x * TOPK,
                      g_cand_i + blockIdx.x * TOPK);
}

// ---------------------------------------------------------------------------
// top-k pass 2: one block merges NB1*TOPK candidates, writes output
// out layout: [TOPK values][TOPK indices-as-float]
// ---------------------------------------------------------------------------
__global__ void __launch_bounds__(256)
topk2_kernel(float* __restrict__ out, int out_size) {
    const int NC = NB1 * TOPK;
    float lv[TOPK]; int li[TOPK];
    #pragma unroll
    for (int k = 0; k < TOPK; k++) { lv[k] = -FLT_MAX; li[k] = INT_MAX; }

    for (int p = threadIdx.x; p < NC; p += 256)
        insert10(lv, li, g_cand_v[p], g_cand_i[p]);

    __shared__ float sv[8 * TOPK];
    __shared__ int   si[8 * TOPK];
    __shared__ float fv[TOPK];
    __shared__ int   fi[TOPK];
    int wid = threadIdx.x >> 5;
    warp_merge10(lv, li, sv + wid * TOPK, si + wid * TOPK);
    __syncthreads();
    if (wid == 0) block_merge10(sv, si, 8, fv, fi);
    __syncthreads();

    if (threadIdx.x < TOPK) {
        int k = threadIdx.x;
        if (k < out_size) out[k] = fv[k];
        if (TOPK + k < out_size) out[TOPK + k] = (float)fi[k];
    }
}

// ---------------------------------------------------------------------------
// kernel_launch
// Inputs: q_indices(i32,32) q_values(f32,32) crow(i32,N+1) indice(i32,nnz)
//         values(f32,nnz) [top_k]
// ---------------------------------------------------------------------------
extern "C" void kernel_launch(void* const* d_in, const int* in_sizes, int n_in,
                              void* d_out, int out_size) {
    const int*   qidx   = (const int*)d_in[0];
    const float* qval   = (const float*)d_in[1];
    const int*   crow   = (const int*)d_in[2];
    const int*   indice = (const int*)d_in[3];
    const float* values = (const float*)d_in[4];

    int qn     = in_sizes[0];
    int n_docs = in_sizes[2] - 1;
    int nnz    = in_sizes[3];
    if (n_docs > MAX_DOCS) n_docs = MAX_DOCS;

    const int SMEM_Q = VOCAB * (int)sizeof(float);
    cudaFuncSetAttribute(score_kernel, cudaFuncAttributeMaxDynamicSharedMemorySize, SMEM_Q);

    zero_kernel<<<512, 256>>>(n_docs);
    score_kernel<<<148, 1024, SMEM_Q>>>(qidx, qval, qn, indice, values, nnz);
    resolve_kernel<<<256, 256>>>(crow, n_docs);
    topk1_kernel<<<NB1, 256>>>(n_docs);
    topk2_kernel<<<1, 256>>>((float*)d_out, out_size);
}

// round 7
// speedup vs baseline: 1.8847x; 1.6517x over previous
#include <cuda_runtime.h>
#include <cfloat>
#include <climits>

#define VOCAB 30522
#define HIT_CAP (1 << 21)
#define CAND_CAP (1 << 20)
#define TOPK 10
#define NB1 128
#define STAGE_CAP 2048

// ---- device scratch (BSS zero-init; every launch restores zeros) ----
__device__ float g_scores[500000];
__device__ int   g_hit_pos[HIT_CAP];
__device__ float g_hit_val[HIT_CAP];
__device__ int   g_nhits;
__device__ int   g_cand_doc[CAND_CAP];
__device__ int   g_ncand;
__device__ float g_blk_v[NB1 * TOPK];
__device__ int   g_blk_i[NB1 * TOPK];

// ---------------------------------------------------------------------------
__global__ void reset_kernel() {
    g_nhits = 0;
    g_ncand = 0;
}

// ---------------------------------------------------------------------------
// score: stream nnz (4x-batched int4 -> MLP>=4), smem qtab lookup,
// CTA-local hit staging (ONE global atomic per CTA)
// ---------------------------------------------------------------------------
__shared__ int   s_cnt;
__global__ void __launch_bounds__(1024, 1)
score_kernel(const int* __restrict__ qidx, const float* __restrict__ qval, int qn,
             const int* __restrict__ indice, const float* __restrict__ values,
             int nnz)
{
    extern __shared__ float qtab[];   // VOCAB floats = 122088 B
    __shared__ int   sc_cnt;
    __shared__ int   sc_pos[STAGE_CAP];
    __shared__ float sc_val[STAGE_CAP];
    __shared__ int   sc_base, sc_flush;

    for (int i = threadIdx.x; i < VOCAB; i += 1024) qtab[i] = 0.0f;
    if (threadIdx.x == 0) sc_cnt = 0;
    __syncthreads();
    if (threadIdx.x < qn) atomicAdd(&qtab[qidx[threadIdx.x]], qval[threadIdx.x]);
    __syncthreads();

    const int gtid = blockIdx.x * 1024 + threadIdx.x;
    const int gsz  = gridDim.x * 1024;
    const int total4 = nnz >> 2;
    const int4* __restrict__ ind4 = (const int4*)indice;

    #define EMIT(q, jj)                                                        \
        if ((q) != 0.0f) {                                                     \
            int p = atomicAdd(&sc_cnt, 1);                                     \
            if (p < STAGE_CAP) {                                               \
                sc_pos[p] = (jj); sc_val[p] = (q) * __ldg(values + (jj));      \
            } else {                                                           \
                int gp = atomicAdd(&g_nhits, 1);                               \
                if (gp < HIT_CAP) {                                            \
                    g_hit_pos[gp] = (jj);                                      \
                    g_hit_val[gp] = (q) * __ldg(values + (jj));                \
                }                                                              \
            }                                                                  \
        }

    int i = gtid;
    for (; i + 3 * gsz < total4; i += 4 * gsz) {
        int4 a = __ldcs(ind4 + i);
        int4 b = __ldcs(ind4 + i + gsz);
        int4 c = __ldcs(ind4 + i + 2 * gsz);
        int4 d = __ldcs(ind4 + i + 3 * gsz);

        float qa0 = qtab[a.x], qa1 = qtab[a.y], qa2 = qtab[a.z], qa3 = qtab[a.w];
        float qb0 = qtab[b.x], qb1 = qtab[b.y], qb2 = qtab[b.z], qb3 = qtab[b.w];
        float qc0 = qtab[c.x], qc1 = qtab[c.y], qc2 = qtab[c.z], qc3 = qtab[c.w];
        float qd0 = qtab[d.x], qd1 = qtab[d.y], qd2 = qtab[d.z], qd3 = qtab[d.w];

        int ja = i << 2, jb = (i + gsz) << 2, jc = (i + 2 * gsz) << 2, jd = (i + 3 * gsz) << 2;
        EMIT(qa0, ja)     EMIT(qa1, ja + 1) EMIT(qa2, ja + 2) EMIT(qa3, ja + 3)
        EMIT(qb0, jb)     EMIT(qb1, jb + 1) EMIT(qb2, jb + 2) EMIT(qb3, jb + 3)
        EMIT(qc0, jc)     EMIT(qc1, jc + 1) EMIT(qc2, jc + 2) EMIT(qc3, jc + 3)
        EMIT(qd0, jd)     EMIT(qd1, jd + 1) EMIT(qd2, jd + 2) EMIT(qd3, jd + 3)
    }
    for (; i < total4; i += gsz) {
        int4 a = __ldcs(ind4 + i);
        float q0 = qtab[a.x], q1 = qtab[a.y], q2 = qtab[a.z], q3 = qtab[a.w];
        int j = i << 2;
        EMIT(q0, j) EMIT(q1, j + 1) EMIT(q2, j + 2) EMIT(q3, j + 3)
    }
    int jt = (total4 << 2) + gtid;
    if (jt < nnz) {
        float q = qtab[indice[jt]];
        EMIT(q, jt)
    }
    #undef EMIT

    // flush staging buffer: ONE global atomic per CTA, coalesced copy
    __syncthreads();
    if (threadIdx.x == 0) {
        int c = sc_cnt; if (c > STAGE_CAP) c = STAGE_CAP;
        int base = atomicAdd(&g_nhits, c);
        if (base + c > HIT_CAP) c = (base < HIT_CAP) ? (HIT_CAP - base) : 0;
        sc_base = base; sc_flush = c;
    }
    __syncthreads();
    for (int t = threadIdx.x; t < sc_flush; t += 1024) {
        g_hit_pos[sc_base + t] = sc_pos[t];
        g_hit_val[sc_base + t] = sc_val[t];
    }
}

// ---------------------------------------------------------------------------
// resolve: binary search crow (int32, L2), scatter-add scores; first toucher
// of a doc (old==0, all contributions positive) appends to candidate list
// (CTA-staged to avoid single-address global atomics)
// ---------------------------------------------------------------------------
__global__ void __launch_bounds__(256)
resolve_kernel(const int* __restrict__ crow, int n_docs) {
    __shared__ int s_cnt2;
    __shared__ int s_doc[STAGE_CAP];
    __shared__ int s_base2, s_flush2;
    if (threadIdx.x == 0) s_cnt2 = 0;
    __syncthreads();

    int nh = g_nhits;
    if (nh > HIT_CAP) nh = HIT_CAP;
    int stride = gridDim.x * blockDim.x;
    for (int t = blockIdx.x * blockDim.x + threadIdx.x; t < nh; t += stride) {
        int j = g_hit_pos[t];
        int lo = 0, hi = n_docs;
        while (lo < hi) {
            int mid = (lo + hi + 1) >> 1;
            if (crow[mid] <= j) lo = mid; else hi = mid - 1;
        }
        float old = atomicAdd(&g_scores[lo], g_hit_val[t]);
        if (old == 0.0f) {
            int p = atomicAdd(&s_cnt2, 1);
            if (p < STAGE_CAP) s_doc[p] = lo;
            else {
                int gp = atomicAdd(&g_ncand, 1);
                if (gp < CAND_CAP) g_cand_doc[gp] = lo;
            }
        }
    }

    __syncthreads();
    if (threadIdx.x == 0) {
        int c = s_cnt2; if (c > STAGE_CAP) c = STAGE_CAP;
        int base = atomicAdd(&g_ncand, c);
        if (base + c > CAND_CAP) c = (base < CAND_CAP) ? (CAND_CAP - base) : 0;
        s_base2 = base; s_flush2 = c;
    }
    __syncthreads();
    for (int t = threadIdx.x; t < s_flush2; t += 256)
        g_cand_doc[s_base2 + t] = s_doc[t];
}

// ---------------------------------------------------------------------------
// top-k helpers (static register indexing ONLY — no local-memory demotion)
// ---------------------------------------------------------------------------
__device__ __forceinline__ void insert10(float* lv, int* li, float s, int d) {
    if (s > lv[TOPK - 1] || (s == lv[TOPK - 1] && d < li[TOPK - 1])) {
        lv[TOPK - 1] = s; li[TOPK - 1] = d;
        #pragma unroll
        for (int k = TOPK - 1; k > 0; k--) {
            bool sw = (lv[k] > lv[k - 1]) ||
                      (lv[k] == lv[k - 1] && li[k] < li[k - 1]);
            if (sw) {
                float tv = lv[k]; lv[k] = lv[k - 1]; lv[k - 1] = tv;
                int   ti = li[k]; li[k] = li[k - 1]; li[k - 1] = ti;
            }
        }
    }
}

// merge 32 per-lane sorted lists (registers); pop-and-shift, static indices
__device__ __forceinline__ void warp_merge10(float* lv, int* li,
                                             float* out_v, int* out_i) {
    int lane = threadIdx.x & 31;
    #pragma unroll
    for (int r = 0; r < TOPK; r++) {
        float bv = lv[0]; int bi = li[0]; int bl = lane;
        #pragma unroll
        for (int off = 16; off; off >>= 1) {
            float ov = __shfl_down_sync(0xffffffffu, bv, off);
            int   oi = __shfl_down_sync(0xffffffffu, bi, off);
            int   ol = __shfl_down_sync(0xffffffffu, bl, off);
            if (ov > bv || (ov == bv && oi < bi)) { bv = ov; bi = oi; bl = ol; }
        }
        bl = __shfl_sync(0xffffffffu, bl, 0);
        float wv = __shfl_sync(0xffffffffu, bv, 0);
        int   wi = __shfl_sync(0xffffffffu, bi, 0);
        if (lane == bl) {
            #pragma unroll
            for (int k = 0; k < TOPK - 1; k++) { lv[k] = lv[k + 1]; li[k] = li[k + 1]; }
            lv[TOPK - 1] = -FLT_MAX; li[TOPK - 1] = INT_MAX;
        }
        if (lane == 0) { out_v[r] = wv; out_i[r] = wi; }
    }
}

// warp 0: load one 10-list per lane from smem into registers, merge
__device__ __forceinline__ void block_merge10(const float* sv, const int* si,
                                              int nwarp, float* out_v, int* out_i) {
    int lane = threadIdx.x & 31;
    float lv[TOPK]; int li[TOPK];
    #pragma unroll
    for (int k = 0; k < TOPK; k++) {
        if (lane < nwarp) { lv[k] = sv[lane * TOPK + k]; li[k] = si[lane * TOPK + k]; }
        else              { lv[k] = -FLT_MAX;            li[k] = INT_MAX;            }
    }
    warp_merge10(lv, li, out_v, out_i);
}

// ---------------------------------------------------------------------------
// top-k pass 1: scan CANDIDATE docs only (~60K), per-block top-10
// ---------------------------------------------------------------------------
__global__ void __launch_bounds__(256)
topk1_kernel() {
    float lv[TOPK]; int li[TOPK];
    #pragma unroll
    for (int k = 0; k < TOPK; k++) { lv[k] = -FLT_MAX; li[k] = INT_MAX; }

    int nc = g_ncand;
    if (nc > CAND_CAP) nc = CAND_CAP;
    int gtid = blockIdx.x * blockDim.x + threadIdx.x;
    int gsz  = gridDim.x * blockDim.x;
    for (int t = gtid; t < nc; t += gsz) {
        int d = g_cand_doc[t];
        insert10(lv, li, g_scores[d], d);
    }

    __shared__ float sv[8 * TOPK];
    __shared__ int   si[8 * TOPK];
    int wid = threadIdx.x >> 5;
    warp_merge10(lv, li, sv + wid * TOPK, si + wid * TOPK);
    __syncthreads();
    if (wid == 0)
        block_merge10(sv, si, 8, g_blk_v + blockIdx.x * TOPK,
                      g_blk_i + blockIdx.x * TOPK);
}

// ---------------------------------------------------------------------------
// top-k pass 2: merge NB1*TOPK block winners, write output
// out layout: [TOPK values][TOPK indices-as-float]
// ---------------------------------------------------------------------------
__global__ void __launch_bounds__(256)
topk2_kernel(float* __restrict__ out, int out_size) {
    const int NC = NB1 * TOPK;
    float lv[TOPK]; int li[TOPK];
    #pragma unroll
    for (int k = 0; k < TOPK; k++) { lv[k] = -FLT_MAX; li[k] = INT_MAX; }

    for (int p = threadIdx.x; p < NC; p += 256)
        insert10(lv, li, g_blk_v[p], g_blk_i[p]);

    __shared__ float sv[8 * TOPK];
    __shared__ int   si[8 * TOPK];
    __shared__ float fv[TOPK];
    __shared__ int   fi[TOPK];
    int wid = threadIdx.x >> 5;
    warp_merge10(lv, li, sv + wid * TOPK, si + wid * TOPK);
    __syncthreads();
    if (wid == 0) block_merge10(sv, si, 8, fv, fi);
    __syncthreads();

    if (threadIdx.x < TOPK) {
        int k = threadIdx.x;
        if (k < out_size) out[k] = fv[k];
        if (TOPK + k < out_size) out[TOPK + k] = (float)fi[k];
    }
}

// ---------------------------------------------------------------------------
// cleanup: re-zero exactly the touched scores (restores all-zero invariant)
// ---------------------------------------------------------------------------
__global__ void __launch_bounds__(256)
cleanup_kernel() {
    int nc = g_ncand;
    if (nc > CAND_CAP) nc = CAND_CAP;
    int stride = gridDim.x * blockDim.x;
    for (int t = blockIdx.x * blockDim.x + threadIdx.x; t < nc; t += stride)
        g_scores[g_cand_doc[t]] = 0.0f;
}

// ---------------------------------------------------------------------------
// kernel_launch
// Inputs: q_indices(i32,32) q_values(f32,32) crow(i32,N+1) indice(i32,nnz)
//         values(f32,nnz) [top_k]
// ---------------------------------------------------------------------------
extern "C" void kernel_launch(void* const* d_in, const int* in_sizes, int n_in,
                              void* d_out, int out_size) {
    const int*   qidx   = (const int*)d_in[0];
    const float* qval   = (const float*)d_in[1];
    const int*   crow   = (const int*)d_in[2];
    const int*   indice = (const int*)d_in[3];
    const float* values = (const float*)d_in[4];

    int qn     = in_sizes[0];
    int n_docs = in_sizes[2] - 1;
    int nnz    = in_sizes[3];

    const int SMEM_Q = VOCAB * (int)sizeof(float);
    cudaFuncSetAttribute(score_kernel, cudaFuncAttributeMaxDynamicSharedMemorySize, SMEM_Q);

    reset_kernel<<<1, 1>>>();
    score_kernel<<<148, 1024, SMEM_Q>>>(qidx, qval, qn, indice, values, nnz);
    resolve_kernel<<<256, 256>>>(crow, n_docs);
    topk1_kernel<<<NB1, 256>>>();
    topk2_kernel<<<1, 256>>>((float*)d_out, out_size);
    cleanup_kernel<<<128, 256>>>();
}